// round 16
// baseline (speedup 1.0000x reference)
#include <cuda_runtime.h>
#include <math_constants.h>

#define B_ 8
#define L_ 2000
#define C_ 256
#define N_ (B_ * C_)            // 2048
#define A10_OFF 4096000ull      // res elements
#define A20_OFF 86016000ull     // res + attn10 elements

// Scratch (allocation-free rule: __device__ globals)
__device__ float g_xT[N_ * L_];    // (B, C, L) == (n, L)

// ---- packed f32x2 helpers (sm_103a FFMA2) ----
static __device__ __forceinline__ unsigned long long fma2(unsigned long long a,
                                                          unsigned long long b,
                                                          unsigned long long c) {
    unsigned long long d;
    asm("fma.rn.f32x2 %0, %1, %2, %3;" : "=l"(d) : "l"(a), "l"(b), "l"(c));
    return d;
}
static __device__ __forceinline__ float2 unpack2(unsigned long long v) {
    float lo, hi;
    asm("mov.b64 {%0, %1}, %2;" : "=f"(lo), "=f"(hi) : "l"(v));
    return make_float2(lo, hi);
}
static __device__ __forceinline__ float ex2(float x) {
    float r;
    asm("ex2.approx.f32 %0, %1;" : "=f"(r) : "f"(x));
    return r;
}
static __device__ __forceinline__ float warp_sum(float v) {
#pragma unroll
    for (int off = 16; off; off >>= 1) v += __shfl_xor_sync(0xffffffffu, v, off);
    return v;
}
static __device__ __forceinline__ float frcp(float x) {
    float r;
    asm("rcp.approx.f32 %0, %1;" : "=f"(r) : "f"(x));
    return r;
}

// ---------------- Kernel A: x (B,L,C) -> xT (B,C,L), 128-bit both sides ----------------
// block (8,32): tx indexes 4-float chunks, ty indexes rows of the 32x32 tile
__global__ void k_transpose_x(const float* __restrict__ x) {
    __shared__ float tile[32][33];
    int b = blockIdx.z;
    int l0 = blockIdx.x * 32, c0 = blockIdx.y * 32;
    int tx = threadIdx.x, ty = threadIdx.y;
    {
        int l = l0 + ty;
        if (l < L_) {
            float4 v = *(const float4*)&x[((size_t)b * L_ + l) * C_ + c0 + 4 * tx];
            tile[ty][4 * tx + 0] = v.x;
            tile[ty][4 * tx + 1] = v.y;
            tile[ty][4 * tx + 2] = v.z;
            tile[ty][4 * tx + 3] = v.w;
        }
    }
    __syncthreads();
    {
        int lbase = l0 + 4 * tx;
        if (lbase + 3 < L_) {
            float4 v = make_float4(tile[4 * tx + 0][ty], tile[4 * tx + 1][ty],
                                   tile[4 * tx + 2][ty], tile[4 * tx + 3][ty]);
            *(float4*)&g_xT[((size_t)b * C_ + c0 + ty) * L_ + lbase] = v;
        }
    }
}

// ---------------- Kernel R: res computed directly in output layout from x ----------------
// grid (100, 8): t = i-block of 20 rows, b = batch. Both branches' folded z2 terms
// for i in [20t, 20t+20) read exactly x rows [20t, 20t+20).
__global__ __launch_bounds__(256, 4) void k_res(
    const float* __restrict__ x,
    const float* __restrict__ wl10, const float* __restrict__ bl10,
    const float* __restrict__ wl20, const float* __restrict__ bl20,
    float* __restrict__ out)
{
    int t = blockIdx.x, b = blockIdx.y;
    int tid = threadIdx.x;

    __shared__ float zsl[20][C_];    // 20 x-rows, full C width (20 KB)
    __shared__ float c1[100];        // folded p10 coefs [r1][j]
    __shared__ float c2[400];        // folded p20 coefs [r2][j]
    __shared__ float d12[20];        // folded bias sum per i_loc: d1[r1] + d2[i_loc]

    // load slab (coalesced: consecutive tid -> consecutive c)
    const float* xb = x + ((size_t)b * L_ + 20 * t) * C_;
    for (int k = tid; k < 20 * C_; k += 256) zsl[k >> 8][k & 255] = xb[k];

    if (tid < 100) {
        int r = tid / 10, j = tid - r * 10;
        c1[tid] = 0.25f * (wl10[(20 * r + 9) * 10 + j] + wl10[(20 * r + 10) * 10 + j]);
    }
    for (int k = tid; k < 400; k += 256) {
        int r = k / 20, j = k - r * 20;
        c2[k] = 0.5f * wl20[(5 * r + 2) * 20 + j];
    }
    if (tid >= 128 && tid < 148) {
        int u = tid - 128;   // i_loc
        int r1 = u % 10;
        d12[u] = 0.25f * (bl10[20 * r1 + 9] + bl10[20 * r1 + 10]) + 0.5f * bl20[5 * u + 2];
    }
    __syncthreads();

    int c = tid;
    float* ob = out + ((size_t)b * L_ + 20 * t) * C_ + c;
#pragma unroll 4
    for (int u = 0; u < 20; u++) {
        int r1 = u % 10;
        int base1 = (u / 10) * 10;
        float acc = d12[u];
#pragma unroll
        for (int j = 0; j < 10; j++) acc += c1[r1 * 10 + j] * zsl[base1 + j][c];
#pragma unroll
        for (int j = 0; j < 20; j++) acc += c2[u * 20 + j] * zsl[j][c];
        ob[(size_t)u * C_] = acc;
    }
}

// ---------------- Kernel B: both branches, bx&1 selects; n = bx>>1 ----------------
__global__ __launch_bounds__(256, 4) void k_branches(
    const float* __restrict__ wq10, const float* __restrict__ bq10,
    const float* __restrict__ wk10, const float* __restrict__ bk10,
    const float* __restrict__ wq20, const float* __restrict__ bq20,
    const float* __restrict__ wk20, const float* __restrict__ bk20,
    float* __restrict__ out)
{
    int bx = blockIdx.x;
    int n = bx >> 1;
    int tid = threadIdx.x, lane = tid & 31, wid = tid >> 5;

    __shared__ float zs[L_];
    __shared__ float2 qb2[L_];     // q duplicated into both halves, pre-scaled by s*log2e
    __shared__ float kb[L_];
    __shared__ float wbuf[800];    // branch-dependent weight staging
    __shared__ float bbuf[40];

    for (int i = tid; i < L_; i += 256) zs[i] = g_xT[(size_t)n * L_ + i];

    if ((bx & 1) == 0) {
        // =================== p = 10 branch ===================
        float* wqs = wbuf;          // 100
        float* wks = wbuf + 100;    // 100
        float* bqs = bbuf;          // 10
        float* bks = bbuf + 10;     // 10
        if (tid < 100) { wqs[tid] = wq10[tid]; wks[tid] = wk10[tid]; }
        if (tid >= 128 && tid < 138) {
            bqs[tid - 128] = bq10[tid - 128];
            bks[tid - 128] = bk10[tid - 128];
        }
        __syncthreads();

        const float s10 = rsqrtf(10.0f) * (float)M_LOG2E;   // fold log2e for ex2
        for (int e = tid; e < L_; e += 256) {
            int wi = e / 10, pi = e - wi * 10;
            unsigned long long aq = 0ull, ak = 0ull;
#pragma unroll
            for (int j = 0; j < 5; j++) {
                unsigned long long zz = *(const unsigned long long*)&zs[wi * 10 + 2 * j];
                aq = fma2(zz, *(const unsigned long long*)&wqs[pi * 10 + 2 * j], aq);
                ak = fma2(zz, *(const unsigned long long*)&wks[pi * 10 + 2 * j], ak);
            }
            float2 q2 = unpack2(aq), k2 = unpack2(ak);
            float qv = (bqs[pi] + q2.x + q2.y) * s10;
            qb2[e] = make_float2(qv, qv);
            kb[pi * 200 + wi] = bks[pi] + k2.x + k2.y;
        }
        __syncthreads();

        float* attn = out + A10_OFF + (size_t)n * 40000;
        const bool t1 = (lane < 18);              // cols 128 + 4*lane < 200
        for (int r0 = wid * 4; r0 < 200; r0 += 32) {
            unsigned long long a0[4][2], a1[4][2];
#pragma unroll
            for (int rr = 0; rr < 4; rr++) {
                a0[rr][0] = a0[rr][1] = 0ull;
                a1[rr][0] = a1[rr][1] = 0ull;
            }
#pragma unroll
            for (int pi = 0; pi < 10; pi++) {
                ulonglong2 kv0 = *(const ulonglong2*)&kb[pi * 200 + 4 * lane];
                ulonglong2 kv1 = make_ulonglong2(0ull, 0ull);
                if (t1) kv1 = *(const ulonglong2*)&kb[pi * 200 + 128 + 4 * lane];
#pragma unroll
                for (int rr = 0; rr < 4; rr++) {
                    unsigned long long qq = *(const unsigned long long*)&qb2[(r0 + rr) * 10 + pi];
                    a0[rr][0] = fma2(qq, kv0.x, a0[rr][0]);
                    a0[rr][1] = fma2(qq, kv0.y, a0[rr][1]);
                    a1[rr][0] = fma2(qq, kv1.x, a1[rr][0]);
                    a1[rr][1] = fma2(qq, kv1.y, a1[rr][1]);
                }
            }
#pragma unroll
            for (int rr = 0; rr < 4; rr++) {
                float2 v00 = unpack2(a0[rr][0]), v01 = unpack2(a0[rr][1]);
                float2 v10 = unpack2(a1[rr][0]), v11 = unpack2(a1[rr][1]);
                // no max subtraction: scores are O(10), ex2 cannot overflow fp32
                v00.x = ex2(v00.x); v00.y = ex2(v00.y);
                v01.x = ex2(v01.x); v01.y = ex2(v01.y);
                float part = v00.x + v00.y + v01.x + v01.y;
                if (t1) {
                    v10.x = ex2(v10.x); v10.y = ex2(v10.y);
                    v11.x = ex2(v11.x); v11.y = ex2(v11.y);
                    part += v10.x + v10.y + v11.x + v11.y;
                }
                float inv = frcp(warp_sum(part));
                float4 s0 = make_float4(v00.x * inv, v00.y * inv, v01.x * inv, v01.y * inv);
                __stcs((float4*)&attn[(size_t)(r0 + rr) * 200 + 4 * lane], s0);
                if (t1) {
                    float4 s1 = make_float4(v10.x * inv, v10.y * inv, v11.x * inv, v11.y * inv);
                    __stcs((float4*)&attn[(size_t)(r0 + rr) * 200 + 128 + 4 * lane], s1);
                }
            }
        }
    } else {
        // =================== p = 20 branch ===================
        float* wqs = wbuf;           // 400
        float* wks = wbuf + 400;     // 400
        float* bqs = bbuf;           // 20
        float* bks = bbuf + 20;      // 20
        for (int t = tid; t < 400; t += 256) { wqs[t] = wq20[t]; wks[t] = wk20[t]; }
        if (tid >= 128 && tid < 148) {
            int u = tid - 128;
            bqs[u] = bq20[u]; bks[u] = bk20[u];
        }
        __syncthreads();

        const float s20 = rsqrtf(20.0f) * (float)M_LOG2E;
        for (int e = tid; e < L_; e += 256) {
            int wi = e / 20, pi = e - wi * 20;
            unsigned long long aq = 0ull, ak = 0ull;
#pragma unroll
            for (int j = 0; j < 10; j++) {
                unsigned long long zz = *(const unsigned long long*)&zs[wi * 20 + 2 * j];
                aq = fma2(zz, *(const unsigned long long*)&wqs[pi * 20 + 2 * j], aq);
                ak = fma2(zz, *(const unsigned long long*)&wks[pi * 20 + 2 * j], ak);
            }
            float2 q2 = unpack2(aq), k2 = unpack2(ak);
            float qv = (bqs[pi] + q2.x + q2.y) * s20;
            qb2[e] = make_float2(qv, qv);
            kb[pi * 100 + wi] = bks[pi] + k2.x + k2.y;
        }
        __syncthreads();

        float* attn = out + A20_OFF + (size_t)n * 10000;
        const bool act = (lane < 25);
        for (int r0 = wid * 4; r0 < 100; r0 += 32) {
            unsigned long long a[4][2];
#pragma unroll
            for (int rr = 0; rr < 4; rr++) { a[rr][0] = a[rr][1] = 0ull; }
#pragma unroll
            for (int pi = 0; pi < 20; pi++) {
                ulonglong2 kv = make_ulonglong2(0ull, 0ull);
                if (act) kv = *(const ulonglong2*)&kb[pi * 100 + 4 * lane];
#pragma unroll
                for (int rr = 0; rr < 4; rr++) {
                    unsigned long long qq = *(const unsigned long long*)&qb2[(r0 + rr) * 20 + pi];
                    a[rr][0] = fma2(qq, kv.x, a[rr][0]);
                    a[rr][1] = fma2(qq, kv.y, a[rr][1]);
                }
            }
#pragma unroll
            for (int rr = 0; rr < 4; rr++) {
                float2 v0 = unpack2(a[rr][0]), v1 = unpack2(a[rr][1]);
                float part = 0.f;
                if (act) {
                    v0.x = ex2(v0.x); v0.y = ex2(v0.y);
                    v1.x = ex2(v1.x); v1.y = ex2(v1.y);
                    part = v0.x + v0.y + v1.x + v1.y;
                }
                float inv = frcp(warp_sum(part));
                if (act) {
                    float4 s = make_float4(v0.x * inv, v0.y * inv, v1.x * inv, v1.y * inv);
                    __stcs((float4*)&attn[(size_t)(r0 + rr) * 100 + 4 * lane], s);
                }
            }
        }
    }
}

extern "C" void kernel_launch(void* const* d_in, const int* in_sizes, int n_in,
                              void* d_out, int out_size) {
    const float* x    = (const float*)d_in[0];
    const float* wq10 = (const float*)d_in[1];
    const float* bq10 = (const float*)d_in[2];
    const float* wk10 = (const float*)d_in[3];
    const float* bk10 = (const float*)d_in[4];
    const float* wl10 = (const float*)d_in[5];
    const float* bl10 = (const float*)d_in[6];
    const float* wq20 = (const float*)d_in[7];
    const float* bq20 = (const float*)d_in[8];
    const float* wk20 = (const float*)d_in[9];
    const float* bk20 = (const float*)d_in[10];
    const float* wl20 = (const float*)d_in[11];
    const float* bl20 = (const float*)d_in[12];
    float* out = (float*)d_out;

    dim3 tb(8, 32);
    dim3 gt((L_ + 31) / 32, C_ / 32, B_);
    k_transpose_x<<<gt, tb>>>(x);
    dim3 gr(L_ / 20, B_);
    k_res<<<gr, 256>>>(x, wl10, bl10, wl20, bl20, out);
    k_branches<<<2 * N_, 256>>>(wq10, bq10, wk10, bk10,
                                wq20, bq20, wk20, bk20, out);
}